// round 2
// baseline (speedup 1.0000x reference)
#include <cuda_runtime.h>
#include <cuda_fp16.h>
#include <cstdint>

#define DINLINE __device__ __forceinline__

// Problem shape (fixed)
static constexpr int M = 2048;
static constexpr int K = 4096;
static constexpr int N = 11008;
static constexpr int G = 128;

// GEMM tiling
static constexpr int BM = 128;
static constexpr int BN = 128;
static constexpr int BK = 32;                 // 32 fp16 = 64B per row
static constexpr int STAGES = 4;
static constexpr int NIT = K / BK;            // 128
static constexpr int A_BYTES = BM * BK * 2;   // 8192
static constexpr int B_BYTES = BN * BK * 2;   // 8192
static constexpr int STAGE_BYTES = A_BYTES + B_BYTES;        // 16384
static constexpr int SMEM_TOTAL = STAGES * STAGE_BYTES;      // 65536

// fp16 scratch (device globals: no allocation allowed)
__device__ __half g_A[(size_t)M * K];   // x in fp16, [M,K] row-major
__device__ __half g_B[(size_t)N * K];   // dequantized W^T, [N,K] row-major

// ---------------------------------------------------------------------------
// Helpers
// ---------------------------------------------------------------------------
DINLINE uint32_t smem_to_u32(const void* p) {
    uint32_t a;
    asm("{ .reg .u64 t; cvta.to.shared.u64 t, %1; cvt.u32.u64 %0, t; }"
        : "=r"(a) : "l"(p));
    return a;
}

#define SW128(off) ((off) ^ (((off) >> 3) & 0x70))

DINLINE void cp_async16(uint32_t saddr, const void* gptr) {
    asm volatile("cp.async.cg.shared.global [%0], [%1], 16;"
                 :: "r"(saddr), "l"(gptr) : "memory");
}
DINLINE void cp_commit() {
    asm volatile("cp.async.commit_group;" ::: "memory");
}
template <int Nn>
DINLINE void cp_wait() {
    asm volatile("cp.async.wait_group %0;" :: "n"(Nn) : "memory");
}

DINLINE void ldsm_x4(uint32_t r[4], uint32_t addr) {
    asm volatile("ldmatrix.sync.aligned.m8n8.x4.shared.b16 {%0,%1,%2,%3}, [%4];"
                 : "=r"(r[0]), "=r"(r[1]), "=r"(r[2]), "=r"(r[3])
                 : "r"(addr));
}

DINLINE void mma16816(float c[4], const uint32_t a[4], const uint32_t b[2]) {
    asm volatile(
        "mma.sync.aligned.m16n8k16.row.col.f32.f16.f16.f32 "
        "{%0,%1,%2,%3}, {%4,%5,%6,%7}, {%8,%9}, {%0,%1,%2,%3};"
        : "+f"(c[0]), "+f"(c[1]), "+f"(c[2]), "+f"(c[3])
        : "r"(a[0]), "r"(a[1]), "r"(a[2]), "r"(a[3]), "r"(b[0]), "r"(b[1]));
}

// ---------------------------------------------------------------------------
// Kernel 1: x fp32 -> fp16
// ---------------------------------------------------------------------------
__global__ __launch_bounds__(256) void cvt_x_kernel(const float* __restrict__ x) {
    size_t i = ((size_t)blockIdx.x * 256 + threadIdx.x) * 4;
    float4 v = *reinterpret_cast<const float4*>(x + i);
    __half2 a = __floats2half2_rn(v.x, v.y);
    __half2 b = __floats2half2_rn(v.z, v.w);
    uint2 u;
    u.x = *reinterpret_cast<uint32_t*>(&a);
    u.y = *reinterpret_cast<uint32_t*>(&b);
    *reinterpret_cast<uint2*>(&g_A[i]) = u;
}

// ---------------------------------------------------------------------------
// Kernel 2: AWQ dequant + transpose -> g_B[N, K] fp16
// Tile: 64 k-rows x 32 int32 cols (= 256 logical n columns) per block.
// ---------------------------------------------------------------------------
__global__ __launch_bounds__(256) void dequant_kernel(
    const int* __restrict__ qweight, const int* __restrict__ qzeros,
    const float* __restrict__ scales) {
    __shared__ int sq[64][33];  // padded against bank conflicts
    const int tid = threadIdx.x;
    const int n8_0 = blockIdx.x * 32;
    const int k0 = blockIdx.y * 64;
    const int g = k0 / G;  // 64 | 128, so single group per tile

#pragma unroll
    for (int i = tid; i < 64 * 32; i += 256) {
        int kr = i >> 5, nc = i & 31;
        sq[kr][nc] = qweight[(size_t)(k0 + kr) * (N / 8) + n8_0 + nc];
    }
    __syncthreads();

#pragma unroll
    for (int t = 0; t < 8; t++) {
        int cc = tid + 256 * t;      // (n_local, k-octet j)
        int nl = cc >> 3;            // 0..255
        int j  = cc & 7;
        int ng = blockIdx.x * 256 + nl;
        int n8l = nl >> 3;
        int m = nl & 7;
        // AWQ inverse order: nibble index = (m>>1) + 4*(m&1)
        int sh = (((m >> 1) + ((m & 1) << 2)) << 2);
        int z = (qzeros[(size_t)g * (N / 8) + n8_0 + n8l] >> sh) & 0xF;
        float s = scales[(size_t)g * N + ng];
        uint4 v;
        uint32_t* vp = reinterpret_cast<uint32_t*>(&v);
#pragma unroll
        for (int pp = 0; pp < 4; pp++) {
            int q0 = (sq[j * 8 + 2 * pp][n8l] >> sh) & 0xF;
            int q1 = (sq[j * 8 + 2 * pp + 1][n8l] >> sh) & 0xF;
            __half2 h = __floats2half2_rn((float)(q0 - z) * s, (float)(q1 - z) * s);
            vp[pp] = *reinterpret_cast<uint32_t*>(&h);
        }
        *reinterpret_cast<uint4*>(&g_B[(size_t)ng * K + k0 + j * 8]) = v;
    }
}

// ---------------------------------------------------------------------------
// Kernel 3: mma.sync fp16 GEMM (NT), 128x128x32 tile, 4-stage cp.async
// out[m,n] = sum_k g_A[m,k] * g_B[n,k]
// ---------------------------------------------------------------------------
__global__ __launch_bounds__(256, 1) void gemm_kernel(float* __restrict__ out) {
    extern __shared__ __align__(1024) char smem[];
    const uint32_t sb = smem_to_u32(smem);
    const int tid = threadIdx.x;
    const int wid = tid >> 5;
    const int lane = tid & 31;
    const int warp_m = wid & 1;   // 2 warps along M (64 rows each)
    const int warp_n = wid >> 1;  // 4 warps along N (32 cols each)

    const __half* __restrict__ gA = g_A + (size_t)blockIdx.y * BM * K;
    const __half* __restrict__ gB = g_B + (size_t)blockIdx.x * BN * K;

    // --- precompute per-lane ldmatrix offsets (low bits only; swizzle-safe) ---
    // A: x4 load covers one m16 x k16 tile; thread t -> matrix j=t/8, row t%8.
    // matrices ordered [m0-7,k0-7],[m8-15,k0-7],[m0-7,k8-15],[m8-15,k8-15]
    const int aj = lane >> 3, arr = lane & 7;
    const int a_moff = ((aj & 1) << 3) + arr;     // 0..15
    const int a_kch  = aj >> 1;                   // 16B chunk within k-half
    uint32_t swA[2];
#pragma unroll
    for (int ks = 0; ks < 2; ks++)
        swA[ks] = SW128((uint32_t)(a_moff * 64 + ks * 32 + a_kch * 16));
    // B: x4 load covers n16 x k16 (two n8 b-fragments); thread t -> matrix j:
    // j = (ntile_in_pair<<1) | kchunk, row = n offset t%8
    const int bj = lane >> 3, brr = lane & 7;
    const int b_noff = ((bj >> 1) << 3) + brr;    // 0..15
    const int b_kch  = bj & 1;
    uint32_t swB[2];
#pragma unroll
    for (int ks = 0; ks < 2; ks++)
        swB[ks] = SW128((uint32_t)(b_noff * 64 + ks * 32 + b_kch * 16));

    float acc[4][4][4];
#pragma unroll
    for (int i = 0; i < 4; i++)
#pragma unroll
        for (int n = 0; n < 4; n++)
#pragma unroll
            for (int e = 0; e < 4; e++) acc[i][n][e] = 0.f;

    auto load_stage = [&](int it) {
        const int st = it & (STAGES - 1);
        const uint32_t sA = sb + st * STAGE_BYTES;
        const uint32_t sB = sA + A_BYTES;
        const __half* pa = gA + it * BK;
        const __half* pb = gB + it * BK;
        // 512 16B-chunks each for A and B; 256 threads -> 2 each
#pragma unroll
        for (int c = tid; c < BM * 4; c += 256) {
            int r = c >> 2, ch = c & 3;
            cp_async16(sA + SW128((uint32_t)(r * 64 + ch * 16)),
                       pa + (size_t)r * K + ch * 8);
        }
#pragma unroll
        for (int c = tid; c < BN * 4; c += 256) {
            int r = c >> 2, ch = c & 3;
            cp_async16(sB + SW128((uint32_t)(r * 64 + ch * 16)),
                       pb + (size_t)r * K + ch * 8);
        }
        cp_commit();
    };

    // Prologue: 3 stages in flight
    load_stage(0); load_stage(1); load_stage(2);

#pragma unroll 1
    for (int it = 0; it < NIT; it++) {
        cp_wait<STAGES - 2>();
        __syncthreads();

        // Prefetch stage it+3 (into the stage freed last iteration)
        if (it + STAGES - 1 < NIT) load_stage(it + STAGES - 1);
        else cp_commit();  // keep group-count bookkeeping uniform

        const int st = it & (STAGES - 1);
        const uint32_t aBase = sb + st * STAGE_BYTES + warp_m * 4096;
        const uint32_t bBase = sb + st * STAGE_BYTES + A_BYTES + warp_n * 2048;

#pragma unroll
        for (int ks = 0; ks < 2; ks++) {
            uint32_t a[4][4];
#pragma unroll
            for (int i = 0; i < 4; i++)
                ldsm_x4(a[i], aBase + i * 1024 + swA[ks]);
            uint32_t b[4][2];
#pragma unroll
            for (int p = 0; p < 2; p++) {
                uint32_t r[4];
                ldsm_x4(r, bBase + p * 1024 + swB[ks]);
                b[2 * p][0] = r[0];  b[2 * p][1] = r[1];
                b[2 * p + 1][0] = r[2]; b[2 * p + 1][1] = r[3];
            }
#pragma unroll
            for (int i = 0; i < 4; i++)
#pragma unroll
                for (int n = 0; n < 4; n++)
                    mma16816(acc[i][n], a[i], b[n]);
        }
        __syncthreads();
    }

    // Epilogue: direct fp32 stores
    const int row_t = lane >> 2;          // 0..7
    const int col_t = (lane & 3) * 2;
#pragma unroll
    for (int i = 0; i < 4; i++) {
        int m0 = blockIdx.y * BM + warp_m * 64 + i * 16 + row_t;
#pragma unroll
        for (int n = 0; n < 4; n++) {
            int c0 = blockIdx.x * BN + warp_n * 32 + n * 8 + col_t;
            float2 v0 = make_float2(acc[i][n][0], acc[i][n][1]);
            float2 v1 = make_float2(acc[i][n][2], acc[i][n][3]);
            *reinterpret_cast<float2*>(out + (size_t)m0 * N + c0) = v0;
            *reinterpret_cast<float2*>(out + (size_t)(m0 + 8) * N + c0) = v1;
        }
    }
}

// ---------------------------------------------------------------------------
// Launch
// ---------------------------------------------------------------------------
extern "C" void kernel_launch(void* const* d_in, const int* in_sizes, int n_in,
                              void* d_out, int out_size) {
    (void)in_sizes; (void)n_in; (void)out_size;
    const float* x       = (const float*)d_in[0];
    const int*   qweight = (const int*)d_in[1];
    const int*   qzeros  = (const int*)d_in[2];
    const float* scales  = (const float*)d_in[3];
    float* out = (float*)d_out;

    cudaFuncSetAttribute(gemm_kernel,
                         cudaFuncAttributeMaxDynamicSharedMemorySize, SMEM_TOTAL);

    cvt_x_kernel<<<(M * K / 4) / 256, 256>>>(x);
    dequant_kernel<<<dim3(N / 256, K / 64), 256>>>(qweight, qzeros, scales);
    gemm_kernel<<<dim3(N / BN, M / BM), 256, SMEM_TOTAL>>>(out);
}

// round 4
// speedup vs baseline: 1.2045x; 1.2045x over previous
#include <cuda_runtime.h>
#include <cuda_fp16.h>
#include <cstdint>

#define DINLINE __device__ __forceinline__

// Problem shape (fixed)
static constexpr int M = 2048;
static constexpr int K = 4096;
static constexpr int N = 11008;
static constexpr int G = 128;

// GEMM tiling
static constexpr int BM = 128;
static constexpr int BN = 256;
static constexpr int BK = 32;                 // 32 fp16 = 64B per row
static constexpr int STAGES = 3;
static constexpr int NIT = K / BK;            // 128
static constexpr int A_BYTES = BM * BK * 2;   // 8192
static constexpr int B_BYTES = BN * BK * 2;   // 16384
static constexpr int STAGE_BYTES = A_BYTES + B_BYTES;        // 24576
static constexpr int SMEM_TOTAL = STAGES * STAGE_BYTES;      // 73728

// fp16 scratch (device globals: no allocation allowed)
__device__ __half g_A[(size_t)M * K];   // x in fp16, [M,K] row-major
__device__ __half g_B[(size_t)N * K];   // dequantized W^T, [N,K] row-major

// ---------------------------------------------------------------------------
// Helpers
// ---------------------------------------------------------------------------
DINLINE uint32_t smem_to_u32(const void* p) {
    uint32_t a;
    asm("{ .reg .u64 t; cvta.to.shared.u64 t, %1; cvt.u32.u64 %0, t; }"
        : "=r"(a) : "l"(p));
    return a;
}

#define SW128(off) ((off) ^ (((off) >> 3) & 0x70))

DINLINE void cp_async16(uint32_t saddr, const void* gptr) {
    asm volatile("cp.async.cg.shared.global [%0], [%1], 16;"
                 :: "r"(saddr), "l"(gptr) : "memory");
}
DINLINE void cp_commit() {
    asm volatile("cp.async.commit_group;" ::: "memory");
}
template <int Nn>
DINLINE void cp_wait() {
    asm volatile("cp.async.wait_group %0;" :: "n"(Nn) : "memory");
}

DINLINE void ldsm_x4(uint32_t r[4], uint32_t addr) {
    asm volatile("ldmatrix.sync.aligned.m8n8.x4.shared.b16 {%0,%1,%2,%3}, [%4];"
                 : "=r"(r[0]), "=r"(r[1]), "=r"(r[2]), "=r"(r[3])
                 : "r"(addr));
}

DINLINE void mma16816(float c[4], const uint32_t a[4], const uint32_t b[2]) {
    asm volatile(
        "mma.sync.aligned.m16n8k16.row.col.f32.f16.f16.f32 "
        "{%0,%1,%2,%3}, {%4,%5,%6,%7}, {%8,%9}, {%0,%1,%2,%3};"
        : "+f"(c[0]), "+f"(c[1]), "+f"(c[2]), "+f"(c[3])
        : "r"(a[0]), "r"(a[1]), "r"(a[2]), "r"(a[3]), "r"(b[0]), "r"(b[1]));
}

// ---------------------------------------------------------------------------
// Kernel 1: x fp32 -> fp16
// ---------------------------------------------------------------------------
__global__ __launch_bounds__(256) void cvt_x_kernel(const float* __restrict__ x) {
    size_t i = ((size_t)blockIdx.x * 256 + threadIdx.x) * 4;
    float4 v = *reinterpret_cast<const float4*>(x + i);
    __half2 a = __floats2half2_rn(v.x, v.y);
    __half2 b = __floats2half2_rn(v.z, v.w);
    uint2 u;
    u.x = *reinterpret_cast<uint32_t*>(&a);
    u.y = *reinterpret_cast<uint32_t*>(&b);
    *reinterpret_cast<uint2*>(&g_A[i]) = u;
}

// ---------------------------------------------------------------------------
// Kernel 2: AWQ dequant + transpose -> g_B[N, K] fp16
// ---------------------------------------------------------------------------
__global__ __launch_bounds__(256) void dequant_kernel(
    const int* __restrict__ qweight, const int* __restrict__ qzeros,
    const float* __restrict__ scales) {
    __shared__ int sq[64][33];  // padded against bank conflicts
    const int tid = threadIdx.x;
    const int n8_0 = blockIdx.x * 32;
    const int k0 = blockIdx.y * 64;
    const int g = k0 / G;

#pragma unroll
    for (int i = tid; i < 64 * 32; i += 256) {
        int kr = i >> 5, nc = i & 31;
        sq[kr][nc] = qweight[(size_t)(k0 + kr) * (N / 8) + n8_0 + nc];
    }
    __syncthreads();

#pragma unroll
    for (int t = 0; t < 8; t++) {
        int cc = tid + 256 * t;
        int nl = cc >> 3;
        int j  = cc & 7;
        int ng = blockIdx.x * 256 + nl;
        int n8l = nl >> 3;
        int m = nl & 7;
        int sh = (((m >> 1) + ((m & 1) << 2)) << 2);  // AWQ inverse order
        int z = (qzeros[(size_t)g * (N / 8) + n8_0 + n8l] >> sh) & 0xF;
        float s = scales[(size_t)g * N + ng];
        uint4 v;
        uint32_t* vp = reinterpret_cast<uint32_t*>(&v);
#pragma unroll
        for (int pp = 0; pp < 4; pp++) {
            int q0 = (sq[j * 8 + 2 * pp][n8l] >> sh) & 0xF;
            int q1 = (sq[j * 8 + 2 * pp + 1][n8l] >> sh) & 0xF;
            __half2 h = __floats2half2_rn((float)(q0 - z) * s, (float)(q1 - z) * s);
            vp[pp] = *reinterpret_cast<uint32_t*>(&h);
        }
        *reinterpret_cast<uint4*>(&g_B[(size_t)ng * K + k0 + j * 8]) = v;
    }
}

// ---------------------------------------------------------------------------
// Kernel 3: mma.sync fp16 GEMM (NT), 128x256x32 tile, warp tile 64x64,
// 3-stage cp.async, one barrier per k-iter.
// Grid: (m_tile, n_tile) -> consecutive CTAs share the same B tile (L2 reuse).
// ---------------------------------------------------------------------------
__global__ __launch_bounds__(256, 1) void gemm_kernel(float* __restrict__ out) {
    extern __shared__ __align__(1024) char smem[];
    const uint32_t sb = smem_to_u32(smem);
    const int tid = threadIdx.x;
    const int wid = tid >> 5;
    const int lane = tid & 31;
    const int warp_m = wid & 1;   // 2 warps along M (64 rows each)
    const int warp_n = wid >> 1;  // 4 warps along N (64 cols each)

    const __half* __restrict__ gA = g_A + (size_t)blockIdx.x * BM * K;
    const __half* __restrict__ gB = g_B + (size_t)blockIdx.y * BN * K;

    // Per-lane ldmatrix offsets (same for A and B tile geometry: 16 rows x 64B)
    const int j8 = lane >> 3, r8 = lane & 7;
    const int moff = ((j8 & 1) << 3) + r8;   // row within 16-row tile (A layout)
    const int kchA = j8 >> 1;                // 16B chunk
    const int noff = ((j8 >> 1) << 3) + r8;  // row within 16-row tile (B layout)
    const int kchB = j8 & 1;
    uint32_t swA[2], swB[2];
#pragma unroll
    for (int ks = 0; ks < 2; ks++) {
        swA[ks] = SW128((uint32_t)(moff * 64 + ks * 32 + kchA * 16));
        swB[ks] = SW128((uint32_t)(noff * 64 + ks * 32 + kchB * 16));
    }

    float acc[4][8][4];
#pragma unroll
    for (int i = 0; i < 4; i++)
#pragma unroll
        for (int n = 0; n < 8; n++)
#pragma unroll
            for (int e = 0; e < 4; e++) acc[i][n][e] = 0.f;

    auto load_stage = [&](int it) {
        const int st = it % STAGES;
        const uint32_t sA = sb + st * STAGE_BYTES;
        const uint32_t sB = sA + A_BYTES;
        const __half* pa = gA + it * BK;
        const __half* pb = gB + it * BK;
#pragma unroll
        for (int c = tid; c < BM * 4; c += 256) {     // 2 per thread
            int r = c >> 2, ch = c & 3;
            cp_async16(sA + SW128((uint32_t)(r * 64 + ch * 16)),
                       pa + (size_t)r * K + ch * 8);
        }
#pragma unroll
        for (int c = tid; c < BN * 4; c += 256) {     // 4 per thread
            int r = c >> 2, ch = c & 3;
            cp_async16(sB + SW128((uint32_t)(r * 64 + ch * 16)),
                       pb + (size_t)r * K + ch * 8);
        }
        cp_commit();
    };

    // Prologue: 2 stages in flight
    load_stage(0); load_stage(1);

#pragma unroll 1
    for (int it = 0; it < NIT; it++) {
        cp_wait<STAGES - 2>();      // stage `it` resident
        __syncthreads();            // everyone done reading slot (it+2)%3

        if (it + STAGES - 1 < NIT) load_stage(it + STAGES - 1);
        else cp_commit();           // uniform group bookkeeping

        const int st = it % STAGES;
        const uint32_t aBase = sb + st * STAGE_BYTES + warp_m * 4096;
        const uint32_t bBase = sb + st * STAGE_BYTES + A_BYTES + warp_n * 4096;

#pragma unroll
        for (int ks = 0; ks < 2; ks++) {
            uint32_t a[4][4];
#pragma unroll
            for (int i = 0; i < 4; i++)
                ldsm_x4(a[i], aBase + i * 1024 + swA[ks]);
            uint32_t b[8][2];
#pragma unroll
            for (int p = 0; p < 4; p++) {
                uint32_t r[4];
                ldsm_x4(r, bBase + p * 1024 + swB[ks]);
                b[2 * p][0] = r[0];     b[2 * p][1] = r[1];
                b[2 * p + 1][0] = r[2]; b[2 * p + 1][1] = r[3];
            }
#pragma unroll
            for (int i = 0; i < 4; i++)
#pragma unroll
                for (int n = 0; n < 8; n++)
                    mma16816(acc[i][n], a[i], b[n]);
        }
    }

    // Epilogue: direct fp32 stores
    const int row_t = lane >> 2;
    const int col_t = (lane & 3) * 2;
#pragma unroll
    for (int i = 0; i < 4; i++) {
        int m0 = blockIdx.x * BM + warp_m * 64 + i * 16 + row_t;
#pragma unroll
        for (int n = 0; n < 8; n++) {
            int c0 = blockIdx.y * BN + warp_n * 64 + n * 8 + col_t;
            float2 v0 = make_float2(acc[i][n][0], acc[i][n][1]);
            float2 v1 = make_float2(acc[i][n][2], acc[i][n][3]);
            *reinterpret_cast<float2*>(out + (size_t)m0 * N + c0) = v0;
            *reinterpret_cast<float2*>(out + (size_t)(m0 + 8) * N + c0) = v1;
        }
    }
}

// ---------------------------------------------------------------------------
// Launch
// ---------------------------------------------------------------------------
extern "C" void kernel_launch(void* const* d_in, const int* in_sizes, int n_in,
                              void* d_out, int out_size) {
    (void)in_sizes; (void)n_in; (void)out_size;
    const float* x       = (const float*)d_in[0];
    const int*   qweight = (const int*)d_in[1];
    const int*   qzeros  = (const int*)d_in[2];
    const float* scales  = (const float*)d_in[3];
    float* out = (float*)d_out;

    cudaFuncSetAttribute(gemm_kernel,
                         cudaFuncAttributeMaxDynamicSharedMemorySize, SMEM_TOTAL);

    cvt_x_kernel<<<(M * K / 4) / 256, 256>>>(x);
    dequant_kernel<<<dim3(N / 256, K / 64), 256>>>(qweight, qzeros, scales);
    // m-tile fastest: consecutive CTAs share the same B tile
    gemm_kernel<<<dim3(M / BM, N / BN), 256, SMEM_TOTAL>>>(out);
}

// round 5
// speedup vs baseline: 1.6664x; 1.3835x over previous
#include <cuda_runtime.h>
#include <cuda_fp16.h>
#include <cstdint>

#define DINLINE __device__ __forceinline__

// Problem shape (fixed)
static constexpr int M = 2048;
static constexpr int K = 4096;
static constexpr int N = 11008;
static constexpr int G = 128;

// GEMM tiling: 128x128x32 CTA tile, 4 warps (warp tile 64x64), 2 CTAs/SM
static constexpr int BM = 128;
static constexpr int BN = 128;
static constexpr int BK = 32;                 // 32 fp16 = 64B per row
static constexpr int STAGES = 4;
static constexpr int NIT = K / BK;            // 128
static constexpr int A_BYTES = BM * BK * 2;   // 8192
static constexpr int B_BYTES = BN * BK * 2;   // 8192
static constexpr int STAGE_BYTES = A_BYTES + B_BYTES;        // 16384
static constexpr int SMEM_TOTAL = STAGES * STAGE_BYTES;      // 65536

// fp16 scratch (device globals: no allocation allowed)
__device__ __half g_A[(size_t)M * K];   // x in fp16, [M,K] row-major
__device__ __half g_B[(size_t)N * K];   // dequantized W^T, [N,K] row-major

// ---------------------------------------------------------------------------
// Helpers
// ---------------------------------------------------------------------------
DINLINE uint32_t smem_to_u32(const void* p) {
    uint32_t a;
    asm("{ .reg .u64 t; cvta.to.shared.u64 t, %1; cvt.u32.u64 %0, t; }"
        : "=r"(a) : "l"(p));
    return a;
}

#define SW128(off) ((off) ^ (((off) >> 3) & 0x70))

DINLINE void cp_async16(uint32_t saddr, const void* gptr) {
    asm volatile("cp.async.cg.shared.global [%0], [%1], 16;"
                 :: "r"(saddr), "l"(gptr) : "memory");
}
DINLINE void cp_commit() {
    asm volatile("cp.async.commit_group;" ::: "memory");
}
template <int Nn>
DINLINE void cp_wait() {
    asm volatile("cp.async.wait_group %0;" :: "n"(Nn) : "memory");
}

DINLINE void ldsm_x4(uint32_t r[4], uint32_t addr) {
    asm volatile("ldmatrix.sync.aligned.m8n8.x4.shared.b16 {%0,%1,%2,%3}, [%4];"
                 : "=r"(r[0]), "=r"(r[1]), "=r"(r[2]), "=r"(r[3])
                 : "r"(addr));
}

DINLINE void mma16816(float c[4], const uint32_t a[4], const uint32_t b[2]) {
    asm volatile(
        "mma.sync.aligned.m16n8k16.row.col.f32.f16.f16.f32 "
        "{%0,%1,%2,%3}, {%4,%5,%6,%7}, {%8,%9}, {%0,%1,%2,%3};"
        : "+f"(c[0]), "+f"(c[1]), "+f"(c[2]), "+f"(c[3])
        : "r"(a[0]), "r"(a[1]), "r"(a[2]), "r"(a[3]), "r"(b[0]), "r"(b[1]));
}

// ---------------------------------------------------------------------------
// Fused prep kernel: blocks [0, 8192) convert x fp32->fp16,
// blocks [8192, 8192+2752) dequantize AWQ -> g_B[N,K] fp16.
// ---------------------------------------------------------------------------
static constexpr int CVT_BLOCKS = (M * K / 4) / 256;           // 8192
static constexpr int DQ_BX = N / 256;                          // 43
static constexpr int DQ_BLOCKS = DQ_BX * (K / 64);             // 2752

__global__ __launch_bounds__(256) void prep_kernel(
    const float* __restrict__ x,
    const int* __restrict__ qweight, const int* __restrict__ qzeros,
    const float* __restrict__ scales) {
    const int tid = threadIdx.x;
    if (blockIdx.x < CVT_BLOCKS) {
        size_t i = ((size_t)blockIdx.x * 256 + tid) * 4;
        float4 v = *reinterpret_cast<const float4*>(x + i);
        __half2 a = __floats2half2_rn(v.x, v.y);
        __half2 b = __floats2half2_rn(v.z, v.w);
        uint2 u;
        u.x = *reinterpret_cast<uint32_t*>(&a);
        u.y = *reinterpret_cast<uint32_t*>(&b);
        *reinterpret_cast<uint2*>(&g_A[i]) = u;
        return;
    }
    __shared__ int sq[64][33];  // padded against bank conflicts
    const int bid = blockIdx.x - CVT_BLOCKS;
    const int bx = bid % DQ_BX;
    const int by = bid / DQ_BX;
    const int n8_0 = bx * 32;
    const int k0 = by * 64;
    const int g = k0 / G;

#pragma unroll
    for (int i = tid; i < 64 * 32; i += 256) {
        int kr = i >> 5, nc = i & 31;
        sq[kr][nc] = qweight[(size_t)(k0 + kr) * (N / 8) + n8_0 + nc];
    }
    __syncthreads();

#pragma unroll
    for (int t = 0; t < 8; t++) {
        int cc = tid + 256 * t;
        int nl = cc >> 3;
        int j  = cc & 7;
        int ng = bx * 256 + nl;
        int n8l = nl >> 3;
        int m = nl & 7;
        int sh = (((m >> 1) + ((m & 1) << 2)) << 2);  // AWQ inverse order
        int z = (qzeros[(size_t)g * (N / 8) + n8_0 + n8l] >> sh) & 0xF;
        float s = scales[(size_t)g * N + ng];
        uint4 v;
        uint32_t* vp = reinterpret_cast<uint32_t*>(&v);
#pragma unroll
        for (int pp = 0; pp < 4; pp++) {
            int q0 = (sq[j * 8 + 2 * pp][n8l] >> sh) & 0xF;
            int q1 = (sq[j * 8 + 2 * pp + 1][n8l] >> sh) & 0xF;
            __half2 h = __floats2half2_rn((float)(q0 - z) * s, (float)(q1 - z) * s);
            vp[pp] = *reinterpret_cast<uint32_t*>(&h);
        }
        *reinterpret_cast<uint4*>(&g_B[(size_t)ng * K + k0 + j * 8]) = v;
    }
}

// ---------------------------------------------------------------------------
// GEMM: mma.sync fp16 (NT), 128x128x32 tile, warp tile 64x64, 4 warps,
// 2 CTAs/SM, 4-stage cp.async, register double-buffered fragments.
// out[m,n] = sum_k g_A[m,k] * g_B[n,k]
// Grid: (m_tile fast, n_tile) -> consecutive CTAs share the same B tile.
// ---------------------------------------------------------------------------
__global__ __launch_bounds__(128, 2) void gemm_kernel(float* __restrict__ out) {
    extern __shared__ __align__(1024) char smem[];
    const uint32_t sb = smem_to_u32(smem);
    const int tid = threadIdx.x;
    const int wid = tid >> 5;
    const int lane = tid & 31;
    const int warp_m = wid & 1;   // 2 warps along M (64 rows each)
    const int warp_n = wid >> 1;  // 2 warps along N (64 cols each)

    const __half* __restrict__ gA = g_A + (size_t)blockIdx.x * BM * K;
    const __half* __restrict__ gB = g_B + (size_t)blockIdx.y * BN * K;

    // Per-lane ldmatrix offsets (16-row x 64B tile geometry)
    const int j8 = lane >> 3, r8 = lane & 7;
    const int moff = ((j8 & 1) << 3) + r8;   // A: row within m16 tile
    const int kchA = j8 >> 1;                // 16B chunk
    const int noff = ((j8 >> 1) << 3) + r8;  // B: row within n16 tile
    const int kchB = j8 & 1;
    uint32_t swA[2], swB[2];
#pragma unroll
    for (int ks = 0; ks < 2; ks++) {
        swA[ks] = SW128((uint32_t)(moff * 64 + ks * 32 + kchA * 16));
        swB[ks] = SW128((uint32_t)(noff * 64 + ks * 32 + kchB * 16));
    }

    float acc[4][8][4];
#pragma unroll
    for (int i = 0; i < 4; i++)
#pragma unroll
        for (int n = 0; n < 8; n++)
#pragma unroll
            for (int e = 0; e < 4; e++) acc[i][n][e] = 0.f;

    auto load_stage = [&](int it) {
        const int st = it & (STAGES - 1);
        const uint32_t sA = sb + st * STAGE_BYTES;
        const uint32_t sB = sA + A_BYTES;
        const __half* pa = gA + it * BK;
        const __half* pb = gB + it * BK;
#pragma unroll
        for (int c = tid; c < BM * 4; c += 128) {     // 4 per thread
            int r = c >> 2, ch = c & 3;
            cp_async16(sA + SW128((uint32_t)(r * 64 + ch * 16)),
                       pa + (size_t)r * K + ch * 8);
        }
#pragma unroll
        for (int c = tid; c < BN * 4; c += 128) {     // 4 per thread
            int r = c >> 2, ch = c & 3;
            cp_async16(sB + SW128((uint32_t)(r * 64 + ch * 16)),
                       pb + (size_t)r * K + ch * 8);
        }
        cp_commit();
    };

    // Prologue: 3 stages in flight
    load_stage(0); load_stage(1); load_stage(2);

    uint32_t a[2][4][4];
    uint32_t b[2][8][2];

    auto load_frags = [&](int ks, uint32_t aBase, uint32_t bBase,
                          uint32_t af[4][4], uint32_t bf[8][2]) {
#pragma unroll
        for (int i = 0; i < 4; i++)
            ldsm_x4(af[i], aBase + i * 1024 + swA[ks]);
#pragma unroll
        for (int p = 0; p < 4; p++) {
            uint32_t r[4];
            ldsm_x4(r, bBase + p * 1024 + swB[ks]);
            bf[2 * p][0] = r[0];     bf[2 * p][1] = r[1];
            bf[2 * p + 1][0] = r[2]; bf[2 * p + 1][1] = r[3];
        }
    };

#pragma unroll 1
    for (int it = 0; it < NIT; it++) {
        cp_wait<STAGES - 2>();      // stage `it` resident
        __syncthreads();            // everyone done reading slot (it+3)&3

        if (it + STAGES - 1 < NIT) load_stage(it + STAGES - 1);
        else cp_commit();           // uniform group bookkeeping

        const int st = it & (STAGES - 1);
        const uint32_t aBase = sb + st * STAGE_BYTES + warp_m * 4096;
        const uint32_t bBase = sb + st * STAGE_BYTES + A_BYTES + warp_n * 4096;

        load_frags(0, aBase, bBase, a[0], b[0]);
        load_frags(1, aBase, bBase, a[1], b[1]);   // in flight over ks=0 MMAs
#pragma unroll
        for (int ks = 0; ks < 2; ks++) {
#pragma unroll
            for (int i = 0; i < 4; i++)
#pragma unroll
                for (int n = 0; n < 8; n++)
                    mma16816(acc[i][n], a[ks][i], b[ks][n]);
        }
    }

    // Epilogue: direct fp32 stores
    const int row_t = lane >> 2;
    const int col_t = (lane & 3) * 2;
#pragma unroll
    for (int i = 0; i < 4; i++) {
        int m0 = blockIdx.x * BM + warp_m * 64 + i * 16 + row_t;
#pragma unroll
        for (int n = 0; n < 8; n++) {
            int c0 = blockIdx.y * BN + warp_n * 64 + n * 8 + col_t;
            float2 v0 = make_float2(acc[i][n][0], acc[i][n][1]);
            float2 v1 = make_float2(acc[i][n][2], acc[i][n][3]);
            *reinterpret_cast<float2*>(out + (size_t)m0 * N + c0) = v0;
            *reinterpret_cast<float2*>(out + (size_t)(m0 + 8) * N + c0) = v1;
        }
    }
}

// ---------------------------------------------------------------------------
// Launch
// ---------------------------------------------------------------------------
extern "C" void kernel_launch(void* const* d_in, const int* in_sizes, int n_in,
                              void* d_out, int out_size) {
    (void)in_sizes; (void)n_in; (void)out_size;
    const float* x       = (const float*)d_in[0];
    const int*   qweight = (const int*)d_in[1];
    const int*   qzeros  = (const int*)d_in[2];
    const float* scales  = (const float*)d_in[3];
    float* out = (float*)d_out;

    cudaFuncSetAttribute(gemm_kernel,
                         cudaFuncAttributeMaxDynamicSharedMemorySize, SMEM_TOTAL);

    prep_kernel<<<CVT_BLOCKS + DQ_BLOCKS, 256>>>(x, qweight, qzeros, scales);
    // m-tile fastest: consecutive CTAs share the same B tile
    gemm_kernel<<<dim3(M / BM, N / BN), 128, SMEM_TOTAL>>>(out);
}